// round 12
// baseline (speedup 1.0000x reference)
#include <cuda_runtime.h>
#include <cstdint>

#define Dn 1024
#define Vn 64
#define TM 32
#define NT 256
#define XR4 132              // xT row stride in floats (f4-major, 33*4)
#define TP 36
#define SLOT_F (32 * TP)
#define PTHRESH 1e-8f

__device__ __align__(16) float g_wt[Dn * Vn];   // g_wt[d*64+v] = hw[v*1024+d]

__global__ void k_tr(const float* __restrict__ hw) {
    __shared__ float t[64][65];
    const int d0 = blockIdx.x * 64;
    const int c  = threadIdx.x & 63;
    const int r4 = threadIdx.x >> 6;
    #pragma unroll
    for (int i = 0; i < 16; i++) t[c][r4 * 16 + i] = hw[(r4 * 16 + i) * Dn + d0 + c];
    __syncthreads();
    #pragma unroll
    for (int i = 0; i < 16; i++) g_wt[(d0 + r4 * 16 + i) * Vn + c] = t[r4 * 16 + i][c];
}

__device__ __forceinline__ unsigned long long ffma2(unsigned long long a,
                                                    unsigned long long b,
                                                    unsigned long long c) {
    unsigned long long d;
    asm("fma.rn.f32x2 %0, %1, %2, %3;" : "=l"(d) : "l"(a), "l"(b), "l"(c));
    return d;
}
__device__ __forceinline__ unsigned long long packdup(float x) {
    unsigned long long d; unsigned u = __float_as_uint(x);
    asm("mov.b64 %0, {%1, %1};" : "=l"(d) : "r"(u));
    return d;
}
__device__ __forceinline__ float f2lo(unsigned long long a) { return __uint_as_float((unsigned)a); }
__device__ __forceinline__ float f2hi(unsigned long long a) { return __uint_as_float((unsigned)(a >> 32)); }

// branchless sigmoid, |z| <= ~0.6 in practice
__device__ __forceinline__ float sigmoid_f(float z) {
    float z2 = z * z;
    return fmaf(z, fmaf(z2, fmaf(z2, fmaf(z2, -2.10813e-04f, 2.08333333e-03f),
                                  -2.08333333e-02f), 0.25f), 0.5f);
}
__device__ __forceinline__ float4 blend4(float4 xv, float4 ev, float g) {
    float4 r;
    r.x = fmaf(ev.x - xv.x, g, xv.x);
    r.y = fmaf(ev.y - xv.y, g, xv.y);
    r.z = fmaf(ev.z - xv.z, g, xv.z);
    r.w = fmaf(ev.w - xv.w, g, xv.w);
    return r;
}

__global__ void __launch_bounds__(NT, 2)
k_fused(const float* __restrict__ xg, const int* __restrict__ iw,
        const float* __restrict__ emb, const float* __restrict__ gate,
        const float* __restrict__ sgate, float* __restrict__ out,
        int idx_off, int has_idx)
{
    extern __shared__ char sm[];
    float*  xT  = (float*)sm;                       // 67584 B  [128 dq][132] per pass
    float*  buf = (float*)(sm + 67584);             // 18432 B  4 tiles [32][36]
    float4* g4s = (float4*)(sm + 67584 + 18432);    // 4096 B
    float4* sg4s= (float4*)(sm + 67584 + 18432 + 4096); // 4096 B

    const int tid  = threadIdx.x;
    const int lane = tid & 31;
    const int wid  = tid >> 5;                      // 0..7
    const int t0   = blockIdx.x * TM;

    for (int i = tid; i < Dn / 4; i += NT) {
        g4s[i]  = ((const float4*)gate)[i];
        sg4s[i] = ((const float4*)sgate)[i];
    }
    // idx dtype: int64 -> high words all zero; int32 -> values 0..63 everywhere.
    int is32 = __syncthreads_or(iw[2 * tid + 1] != 0);

    float garr[4], sgp[4], sgv[4];
    int itarr[4];

    // ---- Phase A pass 0: full-row g; x1 half0 -> xT ----
    #pragma unroll
    for (int j = 0; j < 4; j++) {
        const int tl = 4 * wid + j, tgk = t0 + tl;
        const int poff4 = (((tl & 3) * 8) + (tl >> 2)) * 4;
        const float4* xr4 = (const float4*)(xg + (size_t)tgk * Dn);
        float4 xv[8];
        #pragma unroll
        for (int k = 0; k < 8; k++) xv[k] = xr4[lane + 32 * k];
        float s = 0.f;
        #pragma unroll
        for (int k = 0; k < 8; k++) {
            float4 gg = g4s[lane + 32 * k];
            s += sigmoid_f(xv[k].x * gg.x) + sigmoid_f(xv[k].y * gg.y)
               + sigmoid_f(xv[k].z * gg.z) + sigmoid_f(xv[k].w * gg.w);
        }
        #pragma unroll
        for (int o = 16; o; o >>= 1) s += __shfl_xor_sync(0xffffffffu, s, o);
        float g = s * (1.0f / 1024.0f);
        int it = is32 ? iw[tgk] : iw[2 * tgk];
        it = min(max(it, 0), Vn - 1);
        const float4* er4 = (const float4*)(emb + (size_t)it * Dn);
        float sp = 0.f;
        #pragma unroll
        for (int k = 0; k < 4; k++) {
            float4 ev = __ldg(er4 + lane + 32 * k);
            float4 x1 = blend4(xv[k], ev, g);
            *(float4*)(xT + (lane + 32 * k) * XR4 + poff4) = x1;
            float4 sc = sg4s[lane + 32 * k];
            sp += sigmoid_f(x1.x * sc.x) + sigmoid_f(x1.y * sc.y)
                + sigmoid_f(x1.z * sc.z) + sigmoid_f(x1.w * sc.w);
        }
        garr[j] = g; itarr[j] = it; sgp[j] = sp;
    }
    __syncthreads();

    // ---- GEMM setup: warp = 32tok x 32v x 128d-per-pass ----
    const int tg = lane >> 2, vg = lane & 3;
    const int vhalf = wid >> 2, wd = wid & 3;

    unsigned long long acc[4][4];
    #pragma unroll
    for (int t = 0; t < 4; t++)
        #pragma unroll
        for (int q = 0; q < 4; q++) acc[t][q] = 0ull;

    auto gemm_pass = [&](int p) {
        const ulonglong2* wq = (const ulonglong2*)
            (g_wt + ((size_t)(p * 512 + wd * 128)) * Vn + vhalf * 32 + vg * 8);
        const float* xb = xT + (wd * 32) * XR4 + tg * 4;
        #pragma unroll 2
        for (int sq = 0; sq < 32; sq++) {
            float4 xt0 = *(const float4*)(xb + sq * XR4);
            float4 xt1 = *(const float4*)(xb + sq * XR4 + 32);
            float4 xt2 = *(const float4*)(xb + sq * XR4 + 64);
            float4 xt3 = *(const float4*)(xb + sq * XR4 + 96);
            const float* xf0 = (const float*)&xt0;
            const float* xf1 = (const float*)&xt1;
            const float* xf2 = (const float*)&xt2;
            const float* xf3 = (const float*)&xt3;
            #pragma unroll
            for (int dd = 0; dd < 4; dd++) {
                ulonglong2 wa = wq[(4 * sq + dd) * 16];
                ulonglong2 wb = wq[(4 * sq + dd) * 16 + 1];
                unsigned long long xd;
                xd = packdup(xf0[dd]);
                acc[0][0] = ffma2(xd, wa.x, acc[0][0]);
                acc[0][1] = ffma2(xd, wa.y, acc[0][1]);
                acc[0][2] = ffma2(xd, wb.x, acc[0][2]);
                acc[0][3] = ffma2(xd, wb.y, acc[0][3]);
                xd = packdup(xf1[dd]);
                acc[1][0] = ffma2(xd, wa.x, acc[1][0]);
                acc[1][1] = ffma2(xd, wa.y, acc[1][1]);
                acc[1][2] = ffma2(xd, wb.x, acc[1][2]);
                acc[1][3] = ffma2(xd, wb.y, acc[1][3]);
                xd = packdup(xf2[dd]);
                acc[2][0] = ffma2(xd, wa.x, acc[2][0]);
                acc[2][1] = ffma2(xd, wa.y, acc[2][1]);
                acc[2][2] = ffma2(xd, wb.x, acc[2][2]);
                acc[2][3] = ffma2(xd, wb.y, acc[2][3]);
                xd = packdup(xf3[dd]);
                acc[3][0] = ffma2(xd, wa.x, acc[3][0]);
                acc[3][1] = ffma2(xd, wa.y, acc[3][1]);
                acc[3][2] = ffma2(xd, wb.x, acc[3][2]);
                acc[3][3] = ffma2(xd, wb.y, acc[3][3]);
            }
        }
    };

    gemm_pass(0);
    __syncthreads();

    // ---- Phase A pass 1: x1 half1 (x re-read from L2) ----
    #pragma unroll
    for (int j = 0; j < 4; j++) {
        const int tl = 4 * wid + j, tgk = t0 + tl;
        const int poff4 = (((tl & 3) * 8) + (tl >> 2)) * 4;
        const float gt = garr[j];
        const float4* xr4 = (const float4*)(xg + (size_t)tgk * Dn);
        const float4* er4 = (const float4*)(emb + (size_t)itarr[j] * Dn);
        float sp = sgp[j];
        #pragma unroll
        for (int k = 0; k < 4; k++) {
            float4 xv = xr4[128 + lane + 32 * k];
            float4 ev = __ldg(er4 + 128 + lane + 32 * k);
            float4 x1 = blend4(xv, ev, gt);
            *(float4*)(xT + (lane + 32 * k) * XR4 + poff4) = x1;
            float4 sc = sg4s[128 + lane + 32 * k];
            sp += sigmoid_f(x1.x * sc.x) + sigmoid_f(x1.y * sc.y)
                + sigmoid_f(x1.z * sc.z) + sigmoid_f(x1.w * sc.w);
        }
        sgp[j] = sp;
    }
    #pragma unroll
    for (int j = 0; j < 4; j++) {
        float s = sgp[j];
        #pragma unroll
        for (int o = 16; o; o >>= 1) s += __shfl_xor_sync(0xffffffffu, s, o);
        sgv[j] = s * (1.0f / 1024.0f);
    }
    __syncthreads();

    gemm_pass(1);

    float la[4][8];
    #pragma unroll
    for (int t = 0; t < 4; t++)
        #pragma unroll
        for (int q = 0; q < 4; q++) {
            la[t][2 * q] = f2lo(acc[t][q]); la[t][2 * q + 1] = f2hi(acc[t][q]);
        }

    // ---- cross-warp reduction: per v-half, 4 d-partials -> slots 0,1 ----
    const int sb = vhalf * 2;
    #define TSTORE(SLOT)                                                          \
        { float* bp = buf + (SLOT) * SLOT_F + (4 * tg) * TP + 8 * vg;             \
          _Pragma("unroll") for (int t = 0; t < 4; t++)                           \
          _Pragma("unroll") for (int vv = 0; vv < 8; vv++)                        \
              bp[t * TP + vv] = la[t][vv]; }
    #define TADD(SLOT)                                                            \
        { const float* bp = buf + (SLOT) * SLOT_F + (4 * tg) * TP + 8 * vg;       \
          _Pragma("unroll") for (int t = 0; t < 4; t++)                           \
          _Pragma("unroll") for (int vv = 0; vv < 8; vv++)                        \
              la[t][vv] += bp[t * TP + vv]; }

    __syncthreads();
    if (wd >= 2) TSTORE(sb + wd - 2);
    __syncthreads();
    if (wd < 2) { TADD(sb + wd); TSTORE(sb + wd); }
    __syncthreads();

    // ---- Phase C: warp = 4 tokens; argmax + peaked softmax ----
    float p0a[4], p1a[4];
    unsigned m0a[4], m1a[4];
    #pragma unroll
    for (int j = 0; j < 4; j++) {
        const int tl = 4 * wid + j;
        const int vh = lane >> 4;
        const float* bp = buf + (vh * 2) * SLOT_F + tl * TP + ((2 * lane) & 31);
        float l0 = bp[0] + bp[SLOT_F];
        float l1 = bp[1] + bp[SLOT_F + 1];
        float m = l0; int mi = 2 * lane;
        if (l1 > m) { m = l1; mi = 2 * lane + 1; }
        #pragma unroll
        for (int o = 16; o; o >>= 1) {
            float om = __shfl_xor_sync(0xffffffffu, m, o);
            int  omi = __shfl_xor_sync(0xffffffffu, mi, o);
            if (om > m || (om == m && omi < mi)) { m = om; mi = omi; }
        }
        float e0 = __expf(l0 - m), e1 = __expf(l1 - m);
        float den = e0 + e1;
        #pragma unroll
        for (int o = 16; o; o >>= 1) den += __shfl_xor_sync(0xffffffffu, den, o);
        float rd = 1.0f / den;
        p0a[j] = e0 * rd; p1a[j] = e1 * rd;
        m0a[j] = __ballot_sync(0xffffffffu, p0a[j] > PTHRESH);
        m1a[j] = __ballot_sync(0xffffffffu, p1a[j] > PTHRESH);
        if (has_idx && lane == 0) out[(size_t)idx_off + (t0 + tl)] = (float)mi;
    }

    // ---- Phase D: gather + blend; h0 x1 recomputed (bitwise-identical), h1 from xT ----
    #pragma unroll
    for (int j = 0; j < 4; j++) {
        const int tl = 4 * wid + j, tgk = t0 + tl;
        const int poff4 = (((tl & 3) * 8) + (tl >> 2)) * 4;
        const float sgj = sgv[j], gt = garr[j];
        const float4* xr4 = (const float4*)(xg + (size_t)tgk * Dn);
        const float4* eg4 = (const float4*)(emb + (size_t)itarr[j] * Dn);
        float4* orow = (float4*)(out + (size_t)tgk * Dn);
        #pragma unroll
        for (int h = 0; h < 2; h++) {
            float4 av[4];
            #pragma unroll
            for (int i = 0; i < 4; i++) av[i] = make_float4(0.f, 0.f, 0.f, 0.f);
            unsigned mm = m0a[j];
            while (mm) {                            // uniform trips (ballot-derived)
                int bb = __ffs(mm) - 1; mm &= mm - 1;
                float p = __shfl_sync(0xffffffffu, p0a[j], bb);
                const float4* er = (const float4*)(emb + (size_t)(2 * bb) * Dn)
                                   + h * 128 + lane;
                #pragma unroll
                for (int i = 0; i < 4; i++) {
                    float4 e = __ldg(er + 32 * i);
                    av[i].x = fmaf(p, e.x, av[i].x); av[i].y = fmaf(p, e.y, av[i].y);
                    av[i].z = fmaf(p, e.z, av[i].z); av[i].w = fmaf(p, e.w, av[i].w);
                }
            }
            mm = m1a[j];
            while (mm) {
                int bb = __ffs(mm) - 1; mm &= mm - 1;
                float p = __shfl_sync(0xffffffffu, p1a[j], bb);
                const float4* er = (const float4*)(emb + (size_t)(2 * bb + 1) * Dn)
                                   + h * 128 + lane;
                #pragma unroll
                for (int i = 0; i < 4; i++) {
                    float4 e = __ldg(er + 32 * i);
                    av[i].x = fmaf(p, e.x, av[i].x); av[i].y = fmaf(p, e.y, av[i].y);
                    av[i].z = fmaf(p, e.z, av[i].z); av[i].w = fmaf(p, e.w, av[i].w);
                }
            }
            #pragma unroll
            for (int i = 0; i < 4; i++) {
                int fo = h * 128 + lane + 32 * i;
                float4 x1v;
                if (h == 0) {
                    float4 xv = xr4[fo];
                    float4 ev = __ldg(eg4 + fo);
                    x1v = blend4(xv, ev, gt);        // same fma sequence as Phase A
                } else {
                    x1v = *(const float4*)(xT + (lane + 32 * i) * XR4 + poff4);
                }
                float4 r;
                r.x = fmaf(sgj, av[i].x - x1v.x, x1v.x);
                r.y = fmaf(sgj, av[i].y - x1v.y, x1v.y);
                r.z = fmaf(sgj, av[i].z - x1v.z, x1v.z);
                r.w = fmaf(sgj, av[i].w - x1v.w, x1v.w);
                orow[fo] = r;
            }
        }
    }
}

extern "C" void kernel_launch(void* const* d_in, const int* in_sizes, int n_in,
                              void* d_out, int out_size) {
    (void)n_in;
    const float* x     = (const float*)d_in[0];
    const int*   idx   = (const int*)d_in[1];
    const float* emb   = (const float*)d_in[2];
    const float* hw    = (const float*)d_in[3];
    const float* gate  = (const float*)d_in[4];
    const float* sgate = (const float*)d_in[5];
    float* out = (float*)d_out;

    const int n_tok   = in_sizes[0] / Dn;
    const int idx_off = in_sizes[0];
    const int has_idx = (out_size >= idx_off + n_tok) ? 1 : 0;

    const int smem_bytes = 67584 + 18432 + 4096 + 4096;   // 94208
    cudaFuncSetAttribute(k_fused, cudaFuncAttributeMaxDynamicSharedMemorySize, smem_bytes);

    k_tr<<<Dn / 64, 256>>>(hw);
    k_fused<<<n_tok / TM, NT, smem_bytes>>>(x, idx, emb, gate, sgate, out,
                                            idx_off, has_idx);
}

// round 13
// speedup vs baseline: 1.7047x; 1.7047x over previous
#include <cuda_runtime.h>
#include <cuda_bf16.h>
#include <cstdint>

#define Dn 1024
#define Vn 64
#define TM 128
#define NT 256
#define ARS 272              // A row stride bytes (136 bf16, conflict-free frags)
#define WRS 272
#define PBS 66               // pbuf row stride (floats)
#define PTHRESH 1e-8f
#define RGAP 2e-3f           // argmax repair margin (approx err ~1e-4)

// smem offsets (bytes)
#define S_AH 0
#define S_AL 34816
#define S_WH 69632
#define S_WL 87040
#define S_PB 104448
#define S_G4 138240
#define S_SG4 142336
#define S_GB 146432
#define S_IT 146944
#define S_TOT 147456

__device__ __align__(16) uint16_t g_whl[8 * 2 * Vn * 128];  // [chunk][hi/lo][v][128] bf16
__device__ __align__(16) float gE[Vn * Vn];                 // E[it][v] = emb[it]·hw[v]

__global__ void k_prepw(const float* __restrict__ hwp) {
    int i = blockIdx.x * blockDim.x + threadIdx.x;   // 65536
    int v = i >> 10, d = i & 1023;
    float w = hwp[v * Dn + d];
    __nv_bfloat16 hb = __float2bfloat16(w);
    float hf = __bfloat162float(hb);
    __nv_bfloat16 lb = __float2bfloat16(w - hf);
    int c = d >> 7, dl = d & 127;
    g_whl[((c * 2 + 0) * Vn + v) * 128 + dl] = __bfloat16_as_ushort(hb);
    g_whl[((c * 2 + 1) * Vn + v) * 128 + dl] = __bfloat16_as_ushort(lb);
}

__global__ void k_prepe(const float* __restrict__ emb, const float* __restrict__ hwp) {
    __shared__ float part[256];
    int it = blockIdx.x, t = threadIdx.x, v = t >> 2, q = t & 3;
    const float4* er = (const float4*)(emb + (size_t)it * Dn) + q * 64;
    const float4* wr = (const float4*)(hwp + (size_t)v * Dn) + q * 64;
    float s = 0.f;
    #pragma unroll 8
    for (int k = 0; k < 64; k++) {
        float4 e = er[k], w = wr[k];
        s = fmaf(e.x, w.x, fmaf(e.y, w.y, fmaf(e.z, w.z, fmaf(e.w, w.w, s))));
    }
    part[t] = s;
    __syncthreads();
    if (q == 0) gE[it * Vn + v] = part[t] + part[t + 1] + part[t + 2] + part[t + 3];
}

__device__ __forceinline__ void mma16816(float* d, uint32_t a0, uint32_t a1,
                                         uint32_t a2, uint32_t a3,
                                         uint32_t b0, uint32_t b1) {
    asm volatile("mma.sync.aligned.m16n8k16.row.col.f32.bf16.bf16.f32 "
                 "{%0,%1,%2,%3}, {%4,%5,%6,%7}, {%8,%9}, {%0,%1,%2,%3};"
                 : "+f"(d[0]), "+f"(d[1]), "+f"(d[2]), "+f"(d[3])
                 : "r"(a0), "r"(a1), "r"(a2), "r"(a3), "r"(b0), "r"(b1));
}
__device__ __forceinline__ uint32_t bpack(float lo, float hi) {
    uint32_t r;
    asm("cvt.rn.bf16x2.f32 %0, %1, %2;" : "=r"(r) : "f"(hi), "f"(lo));
    return r;
}
__device__ __forceinline__ float sigmoid_f(float z) {
    float z2 = z * z;
    return fmaf(z, fmaf(z2, fmaf(z2, fmaf(z2, -2.10813e-04f, 2.08333333e-03f),
                                  -2.08333333e-02f), 0.25f), 0.5f);
}
__device__ __forceinline__ float sig4(float4 x, float4 g) {
    return sigmoid_f(x.x * g.x) + sigmoid_f(x.y * g.y)
         + sigmoid_f(x.z * g.z) + sigmoid_f(x.w * g.w);
}
__device__ __forceinline__ float4 blend4(float4 xv, float4 ev, float g) {
    float4 r;
    r.x = fmaf(ev.x - xv.x, g, xv.x);
    r.y = fmaf(ev.y - xv.y, g, xv.y);
    r.z = fmaf(ev.z - xv.z, g, xv.z);
    r.w = fmaf(ev.w - xv.w, g, xv.w);
    return r;
}

__global__ void __launch_bounds__(NT, 1)
k_fused(const float* __restrict__ xg, const int* __restrict__ iw,
        const float* __restrict__ emb, const float* __restrict__ hwp,
        const float* __restrict__ gate, const float* __restrict__ sgate,
        float* __restrict__ out, int idx_off, int has_idx)
{
    extern __shared__ char sm[];
    float4* g4s  = (float4*)(sm + S_G4);
    float4* sg4s = (float4*)(sm + S_SG4);
    float*  gbuf = (float*)(sm + S_GB);
    int*    itb  = (int*)(sm + S_IT);
    float*  pbuf = (float*)(sm + S_PB);

    const int tid = threadIdx.x, lane = tid & 31, w = tid >> 5;
    const int t0 = blockIdx.x * TM;
    const int tok0 = w * 16;

    g4s[tid]  = ((const float4*)gate)[tid];
    sg4s[tid] = ((const float4*)sgate)[tid];
    int is32 = __syncthreads_or(iw[2 * tid + 1] != 0);   // idx dtype detect
    if (tid < TM) {
        int it = is32 ? iw[t0 + tid] : iw[2 * (t0 + tid)];
        itb[tid] = min(max(it, 0), Vn - 1);
    }
    __syncthreads();

    float dfr[8][4];
    #pragma unroll
    for (int nt = 0; nt < 8; nt++)
        #pragma unroll
        for (int q = 0; q < 4; q++) dfr[nt][q] = 0.f;
    float gpart[16];
    #pragma unroll
    for (int i = 0; i < 16; i++) gpart[i] = 0.f;

    const int r  = lane >> 2;
    const int cc = (lane & 3) * 2;

    // ---- chunk loop: stage W + A(raw x, bf16 hi/lo), 24 MMAs/warp/kstep ----
    for (int c = 0; c < 8; c++) {
        {   // W chunk stage
            int v = tid >> 2, part = tid & 3;
            const uint4* srcH = (const uint4*)(g_whl + (c * 2 + 0) * Vn * 128);
            const uint4* srcL = (const uint4*)(g_whl + (c * 2 + 1) * Vn * 128);
            #pragma unroll
            for (int j = 0; j < 4; j++) {
                int si = v * 16 + part * 4 + j;
                *(uint4*)(sm + S_WH + v * WRS + (part * 4 + j) * 16) = srcH[si];
                *(uint4*)(sm + S_WL + v * WRS + (part * 4 + j) * 16) = srcL[si];
            }
        }
        #pragma unroll
        for (int i = 0; i < 16; i++) {                  // A stage + g partial
            int tl = tok0 + i;
            float4 xv = ((const float4*)(xg + (size_t)(t0 + tl) * Dn))[c * 32 + lane];
            gpart[i] += sig4(xv, g4s[c * 32 + lane]);
            __nv_bfloat16 hx = __float2bfloat16(xv.x), hy = __float2bfloat16(xv.y);
            __nv_bfloat16 hz = __float2bfloat16(xv.z), hw4 = __float2bfloat16(xv.w);
            uint32_t h01 = (uint32_t)__bfloat16_as_ushort(hx)
                         | ((uint32_t)__bfloat16_as_ushort(hy) << 16);
            uint32_t h23 = (uint32_t)__bfloat16_as_ushort(hz)
                         | ((uint32_t)__bfloat16_as_ushort(hw4) << 16);
            uint32_t l01 = bpack(xv.x - __bfloat162float(hx), xv.y - __bfloat162float(hy));
            uint32_t l23 = bpack(xv.z - __bfloat162float(hz), xv.w - __bfloat162float(hw4));
            *(uint2*)(sm + S_AH + tl * ARS + lane * 8) = make_uint2(h01, h23);
            *(uint2*)(sm + S_AL + tl * ARS + lane * 8) = make_uint2(l01, l23);
        }
        __syncthreads();
        #pragma unroll
        for (int ks = 0; ks < 8; ks++) {
            const char* aH = sm + S_AH + (tok0 + r) * ARS + (ks * 16 + cc) * 2;
            const char* aL = sm + S_AL + (tok0 + r) * ARS + (ks * 16 + cc) * 2;
            uint32_t ah0 = *(const uint32_t*)aH;
            uint32_t ah1 = *(const uint32_t*)(aH + 8 * ARS);
            uint32_t ah2 = *(const uint32_t*)(aH + 16);
            uint32_t ah3 = *(const uint32_t*)(aH + 8 * ARS + 16);
            uint32_t al0 = *(const uint32_t*)aL;
            uint32_t al1 = *(const uint32_t*)(aL + 8 * ARS);
            uint32_t al2 = *(const uint32_t*)(aL + 16);
            uint32_t al3 = *(const uint32_t*)(aL + 8 * ARS + 16);
            #pragma unroll
            for (int nt = 0; nt < 8; nt++) {
                int n = nt * 8 + r;
                const char* bH = sm + S_WH + n * WRS + (ks * 16 + cc) * 2;
                const char* bL = sm + S_WL + n * WRS + (ks * 16 + cc) * 2;
                uint32_t bh0 = *(const uint32_t*)bH;
                uint32_t bh1 = *(const uint32_t*)(bH + 16);
                uint32_t bl0 = *(const uint32_t*)bL;
                uint32_t bl1 = *(const uint32_t*)(bL + 16);
                mma16816(dfr[nt], ah0, ah1, ah2, ah3, bh0, bh1);
                mma16816(dfr[nt], al0, al1, al2, al3, bh0, bh1);
                mma16816(dfr[nt], ah0, ah1, ah2, ah3, bl0, bl1);
            }
        }
        __syncthreads();
    }

    // ---- Y -> pbuf; g finalize ----
    #pragma unroll
    for (int nt = 0; nt < 8; nt++) {
        *(float2*)(pbuf + (tok0 + r) * PBS + nt * 8 + cc)     = make_float2(dfr[nt][0], dfr[nt][1]);
        *(float2*)(pbuf + (tok0 + r + 8) * PBS + nt * 8 + cc) = make_float2(dfr[nt][2], dfr[nt][3]);
    }
    #pragma unroll
    for (int i = 0; i < 16; i++) {
        float s = gpart[i];
        #pragma unroll
        for (int o = 16; o; o >>= 1) s += __shfl_xor_sync(0xffffffffu, s, o);
        if (lane == 0) gbuf[tok0 + i] = s * (1.0f / 1024.0f);
    }
    __syncthreads();

    // ---- Phase C: logits = Y + g(E - Y); argmax (exact repair) + softmax ----
    for (int i = 0; i < 16; i++) {
        int t = tok0 + i, it = itb[t];
        float g = gbuf[t];
        float2 Y = *(float2*)(pbuf + t * PBS + 2 * lane);
        float2 Ev = __ldg((const float2*)(gE + it * Vn) + lane);
        float l0 = fmaf(g, Ev.x - Y.x, Y.x);
        float l1 = fmaf(g, Ev.y - Y.y, Y.y);
        float m = l0; int mi = 2 * lane;
        if (l1 > m) { m = l1; mi = 2 * lane + 1; }
        #pragma unroll
        for (int o = 16; o; o >>= 1) {
            float om = __shfl_xor_sync(0xffffffffu, m, o);
            int  omi = __shfl_xor_sync(0xffffffffu, mi, o);
            if (om > m || (om == m && omi < mi)) { m = om; mi = omi; }
        }
        float thr = m - RGAP;
        unsigned cm0 = __ballot_sync(0xffffffffu, l0 > thr);
        unsigned cm1 = __ballot_sync(0xffffffffu, l1 > thr);
        if (__popc(cm0) + __popc(cm1) > 1) {        // rare exact repair
            const float4* xr = (const float4*)(xg + (size_t)(t0 + t) * Dn);
            const float4* er = (const float4*)(emb + (size_t)it * Dn);
            float best = -1e30f; int bi = Vn;
            #pragma unroll
            for (int half = 0; half < 2; half++) {
                unsigned mm = half ? cm1 : cm0;
                while (mm) {
                    int v = 2 * (__ffs(mm) - 1) + half; mm &= mm - 1;
                    const float4* wr = (const float4*)(hwp + (size_t)v * Dn);
                    float s = 0.f;
                    #pragma unroll
                    for (int k = 0; k < 8; k++) {
                        float4 xv = xr[lane + 32 * k];
                        float4 ev = __ldg(er + lane + 32 * k);
                        float4 wv = __ldg(wr + lane + 32 * k);
                        float4 x1 = blend4(xv, ev, g);
                        s = fmaf(x1.x, wv.x, fmaf(x1.y, wv.y,
                            fmaf(x1.z, wv.z, fmaf(x1.w, wv.w, s))));
                    }
                    #pragma unroll
                    for (int o = 16; o; o >>= 1) s += __shfl_xor_sync(0xffffffffu, s, o);
                    if (s > best || (s == best && v < bi)) { best = s; bi = v; }
                }
            }
            mi = bi;
        }
        float e0 = __expf(l0 - m), e1 = __expf(l1 - m);
        float den = e0 + e1;
        #pragma unroll
        for (int o = 16; o; o >>= 1) den += __shfl_xor_sync(0xffffffffu, den, o);
        float rd = 1.0f / den;
        *(float2*)(pbuf + t * PBS + 2 * lane) = make_float2(e0 * rd, e1 * rd);
        if (has_idx && lane == 0) out[(size_t)idx_off + (t0 + t)] = (float)mi;
    }
    __syncthreads();

    // ---- Phase D: x1 recompute in regs; sg; sparse gather; blend; store ----
    for (int i = 0; i < 16; i++) {
        int t = tok0 + i, it = itb[t];
        float g = gbuf[t];
        const float4* xr4 = (const float4*)(xg + (size_t)(t0 + t) * Dn);
        const float4* er4 = (const float4*)(emb + (size_t)it * Dn);
        float4 x1[8];
        float sp = 0.f;
        #pragma unroll
        for (int k = 0; k < 8; k++) {
            float4 xv = xr4[lane + 32 * k];
            float4 ev = __ldg(er4 + lane + 32 * k);
            x1[k] = blend4(xv, ev, g);
            sp += sig4(x1[k], sg4s[lane + 32 * k]);
        }
        #pragma unroll
        for (int o = 16; o; o >>= 1) sp += __shfl_xor_sync(0xffffffffu, sp, o);
        float sg = sp * (1.0f / 1024.0f);

        float2 pv = *(float2*)(pbuf + t * PBS + 2 * lane);
        unsigned m0 = __ballot_sync(0xffffffffu, pv.x > PTHRESH);
        unsigned m1 = __ballot_sync(0xffffffffu, pv.y > PTHRESH);
        float4 av[8];
        #pragma unroll
        for (int k = 0; k < 8; k++) av[k] = make_float4(0.f, 0.f, 0.f, 0.f);
        unsigned mm = m0;
        while (mm) {                                    // uniform trips (ballot)
            int bb = __ffs(mm) - 1; mm &= mm - 1;
            float p = __shfl_sync(0xffffffffu, pv.x, bb);
            const float4* er = (const float4*)(emb + (size_t)(2 * bb) * Dn);
            #pragma unroll
            for (int k = 0; k < 8; k++) {
                float4 e = __ldg(er + lane + 32 * k);
                av[k].x = fmaf(p, e.x, av[k].x); av[k].y = fmaf(p, e.y, av[k].y);
                av[k].z = fmaf(p, e.z, av[k].z); av[k].w = fmaf(p, e.w, av[k].w);
            }
        }
        mm = m1;
        while (mm) {
            int bb = __ffs(mm) - 1; mm &= mm - 1;
            float p = __shfl_sync(0xffffffffu, pv.y, bb);
            const float4* er = (const float4*)(emb + (size_t)(2 * bb + 1) * Dn);
            #pragma unroll
            for (int k = 0; k < 8; k++) {
                float4 e = __ldg(er + lane + 32 * k);
                av[k].x = fmaf(p, e.x, av[k].x); av[k].y = fmaf(p, e.y, av[k].y);
                av[k].z = fmaf(p, e.z, av[k].z); av[k].w = fmaf(p, e.w, av[k].w);
            }
        }
        float4* orow = (float4*)(out + (size_t)(t0 + t) * Dn);
        #pragma unroll
        for (int k = 0; k < 8; k++) {
            float4 rr;
            rr.x = fmaf(sg, av[k].x - x1[k].x, x1[k].x);
            rr.y = fmaf(sg, av[k].y - x1[k].y, x1[k].y);
            rr.z = fmaf(sg, av[k].z - x1[k].z, x1[k].z);
            rr.w = fmaf(sg, av[k].w - x1[k].w, x1[k].w);
            orow[lane + 32 * k] = rr;
        }
    }
}

extern "C" void kernel_launch(void* const* d_in, const int* in_sizes, int n_in,
                              void* d_out, int out_size) {
    (void)n_in;
    const float* x     = (const float*)d_in[0];
    const int*   idx   = (const int*)d_in[1];
    const float* emb   = (const float*)d_in[2];
    const float* hwp   = (const float*)d_in[3];
    const float* gate  = (const float*)d_in[4];
    const float* sgate = (const float*)d_in[5];
    float* out = (float*)d_out;

    const int n_tok   = in_sizes[0] / Dn;
    const int idx_off = in_sizes[0];
    const int has_idx = (out_size >= idx_off + n_tok) ? 1 : 0;

    cudaFuncSetAttribute(k_fused, cudaFuncAttributeMaxDynamicSharedMemorySize, S_TOT);
    k_prepw<<<(Vn * Dn) / 256, 256>>>(hwp);
    k_prepe<<<Vn, 256>>>(emb, hwp);
    k_fused<<<n_tok / TM, NT, S_TOT>>>(x, idx, emb, hwp, gate, sgate, out,
                                       idx_off, has_idx);
}

// round 14
// speedup vs baseline: 1.9039x; 1.1168x over previous
#include <cuda_runtime.h>
#include <cuda_bf16.h>
#include <cstdint>

#define Dn 1024
#define Vn 64
#define TM 64
#define NT 256
#define ARS 272              // A row stride bytes (128 bf16 + pad)
#define WRS 272
#define PBS 66               // pbuf row stride (floats)
#define PTHRESH 1e-8f
#define RGAP 2e-3f           // argmax repair margin (approx err ~1e-4)

// smem offsets (bytes)
#define S_AH 0
#define S_AL 17408
#define S_WH 34816
#define S_WL 52224
#define S_PB 69632
#define S_G4 86528
#define S_SG4 90624
#define S_GB 94720
#define S_IT 94976
#define S_TOT 95232

__device__ __align__(16) uint16_t g_whl[8 * 2 * Vn * 128];  // [chunk][hi/lo][v][128] bf16
__device__ __align__(16) float gE[Vn * Vn];                 // E[it][v] = emb[it]·hw[v]

__global__ void k_prepw(const float* __restrict__ hwp) {
    int i = blockIdx.x * blockDim.x + threadIdx.x;   // 65536
    int v = i >> 10, d = i & 1023;
    float w = hwp[v * Dn + d];
    __nv_bfloat16 hb = __float2bfloat16(w);
    float hf = __bfloat162float(hb);
    __nv_bfloat16 lb = __float2bfloat16(w - hf);
    int c = d >> 7, dl = d & 127;
    g_whl[((c * 2 + 0) * Vn + v) * 128 + dl] = __bfloat16_as_ushort(hb);
    g_whl[((c * 2 + 1) * Vn + v) * 128 + dl] = __bfloat16_as_ushort(lb);
}

__global__ void k_prepe(const float* __restrict__ emb, const float* __restrict__ hwp) {
    __shared__ float part[256];
    int it = blockIdx.x, t = threadIdx.x, v = t >> 2, q = t & 3;
    const float4* er = (const float4*)(emb + (size_t)it * Dn) + q * 64;
    const float4* wr = (const float4*)(hwp + (size_t)v * Dn) + q * 64;
    float s = 0.f;
    #pragma unroll 8
    for (int k = 0; k < 64; k++) {
        float4 e = er[k], w = wr[k];
        s = fmaf(e.x, w.x, fmaf(e.y, w.y, fmaf(e.z, w.z, fmaf(e.w, w.w, s))));
    }
    part[t] = s;
    __syncthreads();
    if (q == 0) gE[it * Vn + v] = part[t] + part[t + 1] + part[t + 2] + part[t + 3];
}

__device__ __forceinline__ void mma16816(float* d, uint32_t a0, uint32_t a1,
                                         uint32_t a2, uint32_t a3,
                                         uint32_t b0, uint32_t b1) {
    asm volatile("mma.sync.aligned.m16n8k16.row.col.f32.bf16.bf16.f32 "
                 "{%0,%1,%2,%3}, {%4,%5,%6,%7}, {%8,%9}, {%0,%1,%2,%3};"
                 : "+f"(d[0]), "+f"(d[1]), "+f"(d[2]), "+f"(d[3])
                 : "r"(a0), "r"(a1), "r"(a2), "r"(a3), "r"(b0), "r"(b1));
}
__device__ __forceinline__ uint32_t bpack(float lo, float hi) {
    uint32_t r;
    asm("cvt.rn.bf16x2.f32 %0, %1, %2;" : "=r"(r) : "f"(hi), "f"(lo));
    return r;
}
__device__ __forceinline__ float sigmoid_f(float z) {
    float z2 = z * z;
    return fmaf(z, fmaf(z2, fmaf(z2, fmaf(z2, -2.10813e-04f, 2.08333333e-03f),
                                  -2.08333333e-02f), 0.25f), 0.5f);
}
__device__ __forceinline__ float sig4(float4 x, float4 g) {
    return sigmoid_f(x.x * g.x) + sigmoid_f(x.y * g.y)
         + sigmoid_f(x.z * g.z) + sigmoid_f(x.w * g.w);
}
__device__ __forceinline__ float4 blend4(float4 xv, float4 ev, float g) {
    float4 r;
    r.x = fmaf(ev.x - xv.x, g, xv.x);
    r.y = fmaf(ev.y - xv.y, g, xv.y);
    r.z = fmaf(ev.z - xv.z, g, xv.z);
    r.w = fmaf(ev.w - xv.w, g, xv.w);
    return r;
}

__global__ void __launch_bounds__(NT, 2)
k_fused(const float* __restrict__ xg, const int* __restrict__ iw,
        const float* __restrict__ emb, const float* __restrict__ hwp,
        const float* __restrict__ gate, const float* __restrict__ sgate,
        float* __restrict__ out, int idx_off, int has_idx)
{
    extern __shared__ char sm[];
    float4* g4s  = (float4*)(sm + S_G4);
    float4* sg4s = (float4*)(sm + S_SG4);
    float*  gbuf = (float*)(sm + S_GB);
    int*    itb  = (int*)(sm + S_IT);
    float*  pbuf = (float*)(sm + S_PB);

    const int tid = threadIdx.x, lane = tid & 31, w = tid >> 5;   // w 0..7
    const int t0 = blockIdx.x * TM;
    const int tokS = w * 8;             // staging / phase C / phase D token base
    const int ms = w & 3, nh = w >> 2;  // MMA: M-slice, N-half
    const int tokM = ms * 16;

    g4s[tid]  = ((const float4*)gate)[tid];
    sg4s[tid] = ((const float4*)sgate)[tid];
    int is32 = __syncthreads_or(iw[2 * tid + 1] != 0);   // idx dtype detect
    if (tid < TM) {
        int it = is32 ? iw[t0 + tid] : iw[2 * (t0 + tid)];
        itb[tid] = min(max(it, 0), Vn - 1);
    }
    __syncthreads();

    float dfr[4][4];
    #pragma unroll
    for (int nt = 0; nt < 4; nt++)
        #pragma unroll
        for (int q = 0; q < 4; q++) dfr[nt][q] = 0.f;
    float gpart[8];
    #pragma unroll
    for (int i = 0; i < 8; i++) gpart[i] = 0.f;

    const int r  = lane >> 2;
    const int cc = (lane & 3) * 2;

    // ---- chunk loop: stage W + A(raw x, bf16 hi/lo), 12 MMAs/warp/kstep ----
    for (int c = 0; c < 8; c++) {
        {   // W chunk stage
            int v = tid >> 2, part = tid & 3;
            const uint4* srcH = (const uint4*)(g_whl + (c * 2 + 0) * Vn * 128);
            const uint4* srcL = (const uint4*)(g_whl + (c * 2 + 1) * Vn * 128);
            #pragma unroll
            for (int j = 0; j < 4; j++) {
                int si = v * 16 + part * 4 + j;
                *(uint4*)(sm + S_WH + v * WRS + (part * 4 + j) * 16) = srcH[si];
                *(uint4*)(sm + S_WL + v * WRS + (part * 4 + j) * 16) = srcL[si];
            }
        }
        #pragma unroll
        for (int i = 0; i < 8; i++) {                  // A stage + g partial
            int tl = tokS + i;
            float4 xv = ((const float4*)(xg + (size_t)(t0 + tl) * Dn))[c * 32 + lane];
            gpart[i] += sig4(xv, g4s[c * 32 + lane]);
            __nv_bfloat16 hx = __float2bfloat16(xv.x), hy = __float2bfloat16(xv.y);
            __nv_bfloat16 hz = __float2bfloat16(xv.z), hw4 = __float2bfloat16(xv.w);
            uint32_t h01 = (uint32_t)__bfloat16_as_ushort(hx)
                         | ((uint32_t)__bfloat16_as_ushort(hy) << 16);
            uint32_t h23 = (uint32_t)__bfloat16_as_ushort(hz)
                         | ((uint32_t)__bfloat16_as_ushort(hw4) << 16);
            uint32_t l01 = bpack(xv.x - __bfloat162float(hx), xv.y - __bfloat162float(hy));
            uint32_t l23 = bpack(xv.z - __bfloat162float(hz), xv.w - __bfloat162float(hw4));
            *(uint2*)(sm + S_AH + tl * ARS + lane * 8) = make_uint2(h01, h23);
            *(uint2*)(sm + S_AL + tl * ARS + lane * 8) = make_uint2(l01, l23);
        }
        __syncthreads();
        #pragma unroll
        for (int ks = 0; ks < 8; ks++) {
            const char* aH = sm + S_AH + (tokM + r) * ARS + (ks * 16 + cc) * 2;
            const char* aL = sm + S_AL + (tokM + r) * ARS + (ks * 16 + cc) * 2;
            uint32_t ah0 = *(const uint32_t*)aH;
            uint32_t ah1 = *(const uint32_t*)(aH + 8 * ARS);
            uint32_t ah2 = *(const uint32_t*)(aH + 16);
            uint32_t ah3 = *(const uint32_t*)(aH + 8 * ARS + 16);
            uint32_t al0 = *(const uint32_t*)aL;
            uint32_t al1 = *(const uint32_t*)(aL + 8 * ARS);
            uint32_t al2 = *(const uint32_t*)(aL + 16);
            uint32_t al3 = *(const uint32_t*)(aL + 8 * ARS + 16);
            #pragma unroll
            for (int nt = 0; nt < 4; nt++) {
                int n = nh * 32 + nt * 8 + r;
                const char* bH = sm + S_WH + n * WRS + (ks * 16 + cc) * 2;
                const char* bL = sm + S_WL + n * WRS + (ks * 16 + cc) * 2;
                uint32_t bh0 = *(const uint32_t*)bH;
                uint32_t bh1 = *(const uint32_t*)(bH + 16);
                uint32_t bl0 = *(const uint32_t*)bL;
                uint32_t bl1 = *(const uint32_t*)(bL + 16);
                mma16816(dfr[nt], ah0, ah1, ah2, ah3, bh0, bh1);
                mma16816(dfr[nt], al0, al1, al2, al3, bh0, bh1);
                mma16816(dfr[nt], ah0, ah1, ah2, ah3, bl0, bl1);
            }
        }
        __syncthreads();
    }

    // ---- Y -> pbuf; g finalize ----
    #pragma unroll
    for (int nt = 0; nt < 4; nt++) {
        int col = nh * 32 + nt * 8 + cc;
        *(float2*)(pbuf + (tokM + r) * PBS + col)     = make_float2(dfr[nt][0], dfr[nt][1]);
        *(float2*)(pbuf + (tokM + r + 8) * PBS + col) = make_float2(dfr[nt][2], dfr[nt][3]);
    }
    #pragma unroll
    for (int i = 0; i < 8; i++) {
        float s = gpart[i];
        #pragma unroll
        for (int o = 16; o; o >>= 1) s += __shfl_xor_sync(0xffffffffu, s, o);
        if (lane == 0) gbuf[tokS + i] = s * (1.0f / 1024.0f);
    }
    __syncthreads();

    // ---- Phase C: logits = Y + g(E - Y); argmax (exact repair) + softmax ----
    for (int i = 0; i < 8; i++) {
        int t = tokS + i, it = itb[t];
        float g = gbuf[t];
        float2 Y = *(float2*)(pbuf + t * PBS + 2 * lane);
        float2 Ev = __ldg((const float2*)(gE + it * Vn) + lane);
        float l0 = fmaf(g, Ev.x - Y.x, Y.x);
        float l1 = fmaf(g, Ev.y - Y.y, Y.y);
        float m = l0; int mi = 2 * lane;
        if (l1 > m) { m = l1; mi = 2 * lane + 1; }
        #pragma unroll
        for (int o = 16; o; o >>= 1) {
            float om = __shfl_xor_sync(0xffffffffu, m, o);
            int  omi = __shfl_xor_sync(0xffffffffu, mi, o);
            if (om > m || (om == m && omi < mi)) { m = om; mi = omi; }
        }
        float thr = m - RGAP;
        unsigned cm0 = __ballot_sync(0xffffffffu, l0 > thr);
        unsigned cm1 = __ballot_sync(0xffffffffu, l1 > thr);
        if (__popc(cm0) + __popc(cm1) > 1) {        // rare exact repair
            const float4* xr = (const float4*)(xg + (size_t)(t0 + t) * Dn);
            const float4* er = (const float4*)(emb + (size_t)it * Dn);
            float best = -1e30f; int bi = Vn;
            #pragma unroll
            for (int half = 0; half < 2; half++) {
                unsigned mm = half ? cm1 : cm0;
                while (mm) {
                    int v = 2 * (__ffs(mm) - 1) + half; mm &= mm - 1;
                    const float4* wr = (const float4*)(hwp + (size_t)v * Dn);
                    float s = 0.f;
                    #pragma unroll
                    for (int k = 0; k < 8; k++) {
                        float4 xv = xr[lane + 32 * k];
                        float4 ev = __ldg(er + lane + 32 * k);
                        float4 wv = __ldg(wr + lane + 32 * k);
                        float4 x1 = blend4(xv, ev, g);
                        s = fmaf(x1.x, wv.x, fmaf(x1.y, wv.y,
                            fmaf(x1.z, wv.z, fmaf(x1.w, wv.w, s))));
                    }
                    #pragma unroll
                    for (int o = 16; o; o >>= 1) s += __shfl_xor_sync(0xffffffffu, s, o);
                    if (s > best || (s == best && v < bi)) { best = s; bi = v; }
                }
            }
            mi = bi;
        }
        float e0 = __expf(l0 - m), e1 = __expf(l1 - m);
        float den = e0 + e1;
        #pragma unroll
        for (int o = 16; o; o >>= 1) den += __shfl_xor_sync(0xffffffffu, den, o);
        float rd = 1.0f / den;
        *(float2*)(pbuf + t * PBS + 2 * lane) = make_float2(e0 * rd, e1 * rd);
        if (has_idx && lane == 0) out[(size_t)idx_off + (t0 + t)] = (float)mi;
    }
    __syncthreads();

    // ---- Phase D: x1 recompute in regs; sg; sparse gather; blend; store ----
    for (int i = 0; i < 8; i++) {
        int t = tokS + i, it = itb[t];
        float g = gbuf[t];
        const float4* xr4 = (const float4*)(xg + (size_t)(t0 + t) * Dn);
        const float4* er4 = (const float4*)(emb + (size_t)it * Dn);
        float4 x1[8];
        float sp = 0.f;
        #pragma unroll
        for (int k = 0; k < 8; k++) {
            float4 xv = xr4[lane + 32 * k];
            float4 ev = __ldg(er4 + lane + 32 * k);
            x1[k] = blend4(xv, ev, g);
            sp += sig4(x1[k], sg4s[lane + 32 * k]);
        }
        #pragma unroll
        for (int o = 16; o; o >>= 1) sp += __shfl_xor_sync(0xffffffffu, sp, o);
        float sg = sp * (1.0f / 1024.0f);

        float2 pv = *(float2*)(pbuf + t * PBS + 2 * lane);
        unsigned m0 = __ballot_sync(0xffffffffu, pv.x > PTHRESH);
        unsigned m1 = __ballot_sync(0xffffffffu, pv.y > PTHRESH);
        float4 av[8];
        #pragma unroll
        for (int k = 0; k < 8; k++) av[k] = make_float4(0.f, 0.f, 0.f, 0.f);
        unsigned mm = m0;
        while (mm) {                                    // uniform trips (ballot)
            int bb = __ffs(mm) - 1; mm &= mm - 1;
            float p = __shfl_sync(0xffffffffu, pv.x, bb);
            const float4* er = (const float4*)(emb + (size_t)(2 * bb) * Dn);
            #pragma unroll
            for (int k = 0; k < 8; k++) {
                float4 e = __ldg(er + lane + 32 * k);
                av[k].x = fmaf(p, e.x, av[k].x); av[k].y = fmaf(p, e.y, av[k].y);
                av[k].z = fmaf(p, e.z, av[k].z); av[k].w = fmaf(p, e.w, av[k].w);
            }
        }
        mm = m1;
        while (mm) {
            int bb = __ffs(mm) - 1; mm &= mm - 1;
            float p = __shfl_sync(0xffffffffu, pv.y, bb);
            const float4* er = (const float4*)(emb + (size_t)(2 * bb + 1) * Dn);
            #pragma unroll
            for (int k = 0; k < 8; k++) {
                float4 e = __ldg(er + lane + 32 * k);
                av[k].x = fmaf(p, e.x, av[k].x); av[k].y = fmaf(p, e.y, av[k].y);
                av[k].z = fmaf(p, e.z, av[k].z); av[k].w = fmaf(p, e.w, av[k].w);
            }
        }
        float4* orow = (float4*)(out + (size_t)(t0 + t) * Dn);
        #pragma unroll
        for (int k = 0; k < 8; k++) {
            float4 rr;
            rr.x = fmaf(sg, av[k].x - x1[k].x, x1[k].x);
            rr.y = fmaf(sg, av[k].y - x1[k].y, x1[k].y);
            rr.z = fmaf(sg, av[k].z - x1[k].z, x1[k].z);
            rr.w = fmaf(sg, av[k].w - x1[k].w, x1[k].w);
            orow[lane + 32 * k] = rr;
        }
    }
}

extern "C" void kernel_launch(void* const* d_in, const int* in_sizes, int n_in,
                              void* d_out, int out_size) {
    (void)n_in;
    const float* x     = (const float*)d_in[0];
    const int*   idx   = (const int*)d_in[1];
    const float* emb   = (const float*)d_in[2];
    const float* hwp   = (const float*)d_in[3];
    const float* gate  = (const float*)d_in[4];
    const float* sgate = (const float*)d_in[5];
    float* out = (float*)d_out;

    const int n_tok   = in_sizes[0] / Dn;
    const int idx_off = in_sizes[0];
    const int has_idx = (out_size >= idx_off + n_tok) ? 1 : 0;

    cudaFuncSetAttribute(k_fused, cudaFuncAttributeMaxDynamicSharedMemorySize, S_TOT);
    k_prepw<<<(Vn * Dn) / 256, 256>>>(hwp);
    k_prepe<<<Vn, 256>>>(emb, hwp);
    k_fused<<<n_tok / TM, NT, S_TOT>>>(x, idx, emb, hwp, gate, sgate, out,
                                       idx_off, has_idx);
}

// round 15
// speedup vs baseline: 2.0840x; 1.0946x over previous
#include <cuda_runtime.h>
#include <cuda_bf16.h>
#include <cstdint>

#define Dn 1024
#define Vn 64
#define TM 64
#define NT 256
#define ARS 272
#define WRS 272
#define PTHRESH 1e-8f
#define RGAP 2e-3f
#define NTOK 32768

// k1 smem offsets
#define S_AH 0
#define S_AL 17408
#define S_WH 34816
#define S_WL 52224
#define S_G4 69632
#define S_TOT 73728

__device__ __align__(16) uint16_t g_whl[8 * 2 * Vn * 128];  // [chunk][hi/lo][v][128] bf16
__device__ __align__(16) float gE[Vn * Vn];                 // E[it][v] = emb[it]·hw[v]
__device__ __align__(16) float gY[NTOK * Vn];               // Y = x·W scratch (8MB)
__device__ __align__(16) float gG[NTOK];                    // g scratch

__global__ void k_prepw(const float* __restrict__ hwp) {
    int i = blockIdx.x * blockDim.x + threadIdx.x;
    int v = i >> 10, d = i & 1023;
    float w = hwp[v * Dn + d];
    __nv_bfloat16 hb = __float2bfloat16(w);
    __nv_bfloat16 lb = __float2bfloat16(w - __bfloat162float(hb));
    int c = d >> 7, dl = d & 127;
    g_whl[((c * 2 + 0) * Vn + v) * 128 + dl] = __bfloat16_as_ushort(hb);
    g_whl[((c * 2 + 1) * Vn + v) * 128 + dl] = __bfloat16_as_ushort(lb);
}

__global__ void k_prepe(const float* __restrict__ emb, const float* __restrict__ hwp) {
    __shared__ float part[256];
    int it = blockIdx.x, t = threadIdx.x, v = t >> 2, q = t & 3;
    const float4* er = (const float4*)(emb + (size_t)it * Dn) + q * 64;
    const float4* wr = (const float4*)(hwp + (size_t)v * Dn) + q * 64;
    float s = 0.f;
    #pragma unroll 8
    for (int k = 0; k < 64; k++) {
        float4 e = er[k], w = wr[k];
        s = fmaf(e.x, w.x, fmaf(e.y, w.y, fmaf(e.z, w.z, fmaf(e.w, w.w, s))));
    }
    part[t] = s;
    __syncthreads();
    if (q == 0) gE[it * Vn + v] = part[t] + part[t + 1] + part[t + 2] + part[t + 3];
}

__device__ __forceinline__ void mma16816(float* d, uint32_t a0, uint32_t a1,
                                         uint32_t a2, uint32_t a3,
                                         uint32_t b0, uint32_t b1) {
    asm volatile("mma.sync.aligned.m16n8k16.row.col.f32.bf16.bf16.f32 "
                 "{%0,%1,%2,%3}, {%4,%5,%6,%7}, {%8,%9}, {%0,%1,%2,%3};"
                 : "+f"(d[0]), "+f"(d[1]), "+f"(d[2]), "+f"(d[3])
                 : "r"(a0), "r"(a1), "r"(a2), "r"(a3), "r"(b0), "r"(b1));
}
__device__ __forceinline__ uint32_t bpack(float lo, float hi) {
    uint32_t r;
    asm("cvt.rn.bf16x2.f32 %0, %1, %2;" : "=r"(r) : "f"(hi), "f"(lo));
    return r;
}
__device__ __forceinline__ float sigmoid_f(float z) {
    float z2 = z * z;
    return fmaf(z, fmaf(z2, fmaf(z2, fmaf(z2, -2.10813e-04f, 2.08333333e-03f),
                                  -2.08333333e-02f), 0.25f), 0.5f);
}
__device__ __forceinline__ float sig4(float4 x, float4 g) {
    return sigmoid_f(x.x * g.x) + sigmoid_f(x.y * g.y)
         + sigmoid_f(x.z * g.z) + sigmoid_f(x.w * g.w);
}
__device__ __forceinline__ float4 blend4(float4 xv, float4 ev, float g) {
    float4 r;
    r.x = fmaf(ev.x - xv.x, g, xv.x);
    r.y = fmaf(ev.y - xv.y, g, xv.y);
    r.z = fmaf(ev.z - xv.z, g, xv.z);
    r.w = fmaf(ev.w - xv.w, g, xv.w);
    return r;
}

// ================= k1: Y = x·W (bf16 hi/lo HMMA) + g =================
__global__ void __launch_bounds__(NT, 2)
k_gemm(const float* __restrict__ xg, const float* __restrict__ gate)
{
    extern __shared__ char sm[];
    float4* g4s = (float4*)(sm + S_G4);

    const int tid = threadIdx.x, lane = tid & 31, w = tid >> 5;
    const int t0 = blockIdx.x * TM;
    const int tokS = w * 8;
    const int ms = w & 3, nh = w >> 2;
    const int tokM = ms * 16;

    g4s[tid] = ((const float4*)gate)[tid];
    __syncthreads();

    float dfr[4][4];
    #pragma unroll
    for (int nt = 0; nt < 4; nt++)
        #pragma unroll
        for (int q = 0; q < 4; q++) dfr[nt][q] = 0.f;
    float gpart[8];
    #pragma unroll
    for (int i = 0; i < 8; i++) gpart[i] = 0.f;

    const int r  = lane >> 2;
    const int cc = (lane & 3) * 2;

    for (int c = 0; c < 8; c++) {
        {   // W chunk stage
            int v = tid >> 2, part = tid & 3;
            const uint4* srcH = (const uint4*)(g_whl + (c * 2 + 0) * Vn * 128);
            const uint4* srcL = (const uint4*)(g_whl + (c * 2 + 1) * Vn * 128);
            #pragma unroll
            for (int j = 0; j < 4; j++) {
                int si = v * 16 + part * 4 + j;
                *(uint4*)(sm + S_WH + v * WRS + (part * 4 + j) * 16) = srcH[si];
                *(uint4*)(sm + S_WL + v * WRS + (part * 4 + j) * 16) = srcL[si];
            }
        }
        #pragma unroll
        for (int i = 0; i < 8; i++) {                  // A stage + g partial
            int tl = tokS + i;
            float4 xv = ((const float4*)(xg + (size_t)(t0 + tl) * Dn))[c * 32 + lane];
            gpart[i] += sig4(xv, g4s[c * 32 + lane]);
            __nv_bfloat16 hx = __float2bfloat16(xv.x), hy = __float2bfloat16(xv.y);
            __nv_bfloat16 hz = __float2bfloat16(xv.z), hw4 = __float2bfloat16(xv.w);
            uint32_t h01 = (uint32_t)__bfloat16_as_ushort(hx)
                         | ((uint32_t)__bfloat16_as_ushort(hy) << 16);
            uint32_t h23 = (uint32_t)__bfloat16_as_ushort(hz)
                         | ((uint32_t)__bfloat16_as_ushort(hw4) << 16);
            uint32_t l01 = bpack(xv.x - __bfloat162float(hx), xv.y - __bfloat162float(hy));
            uint32_t l23 = bpack(xv.z - __bfloat162float(hz), xv.w - __bfloat162float(hw4));
            *(uint2*)(sm + S_AH + tl * ARS + lane * 8) = make_uint2(h01, h23);
            *(uint2*)(sm + S_AL + tl * ARS + lane * 8) = make_uint2(l01, l23);
        }
        __syncthreads();
        #pragma unroll
        for (int ks = 0; ks < 8; ks++) {
            const char* aH = sm + S_AH + (tokM + r) * ARS + (ks * 16 + cc) * 2;
            const char* aL = sm + S_AL + (tokM + r) * ARS + (ks * 16 + cc) * 2;
            uint32_t ah0 = *(const uint32_t*)aH;
            uint32_t ah1 = *(const uint32_t*)(aH + 8 * ARS);
            uint32_t ah2 = *(const uint32_t*)(aH + 16);
            uint32_t ah3 = *(const uint32_t*)(aH + 8 * ARS + 16);
            uint32_t al0 = *(const uint32_t*)aL;
            uint32_t al1 = *(const uint32_t*)(aL + 8 * ARS);
            uint32_t al2 = *(const uint32_t*)(aL + 16);
            uint32_t al3 = *(const uint32_t*)(aL + 8 * ARS + 16);
            #pragma unroll
            for (int nt = 0; nt < 4; nt++) {
                int n = nh * 32 + nt * 8 + r;
                const char* bH = sm + S_WH + n * WRS + (ks * 16 + cc) * 2;
                const char* bL = sm + S_WL + n * WRS + (ks * 16 + cc) * 2;
                uint32_t bh0 = *(const uint32_t*)bH;
                uint32_t bh1 = *(const uint32_t*)(bH + 16);
                uint32_t bl0 = *(const uint32_t*)bL;
                uint32_t bl1 = *(const uint32_t*)(bL + 16);
                mma16816(dfr[nt], ah0, ah1, ah2, ah3, bh0, bh1);
                mma16816(dfr[nt], al0, al1, al2, al3, bh0, bh1);
                mma16816(dfr[nt], ah0, ah1, ah2, ah3, bl0, bl1);
            }
        }
        __syncthreads();
    }

    #pragma unroll
    for (int nt = 0; nt < 4; nt++) {
        int col = nh * 32 + nt * 8 + cc;
        *(float2*)(gY + (size_t)(t0 + tokM + r) * Vn + col)
            = make_float2(dfr[nt][0], dfr[nt][1]);
        *(float2*)(gY + (size_t)(t0 + tokM + r + 8) * Vn + col)
            = make_float2(dfr[nt][2], dfr[nt][3]);
    }
    #pragma unroll
    for (int i = 0; i < 8; i++) {
        float s = gpart[i];
        #pragma unroll
        for (int o = 16; o; o >>= 1) s += __shfl_xor_sync(0xffffffffu, s, o);
        if (lane == 0) gG[t0 + tokS + i] = s * (1.0f / 1024.0f);
    }
}

// ================= k2: warp-per-token elementwise + softmax + gather =================
__global__ void __launch_bounds__(256)
k_post(const float* __restrict__ xg, const int* __restrict__ iw,
       const float* __restrict__ emb, const float* __restrict__ hwp,
       const float* __restrict__ sgate, float* __restrict__ out,
       int idx_off, int has_idx)
{
    __shared__ float4 sg4s[256];
    const int tid = threadIdx.x, lane = tid & 31, w = tid >> 5;
    const int t = blockIdx.x * 8 + w;

    sg4s[tid] = ((const float4*)sgate)[tid];
    // idx dtype detect: sample 256 tokens in [0,16384) -> in-bounds either dtype
    int soff = (blockIdx.x * 256 + tid) & 16383;
    int is32 = __syncthreads_or(iw[2 * soff + 1] != 0);

    int it = is32 ? iw[t] : iw[2 * t];
    it = min(max(it, 0), Vn - 1);
    const float g = gG[t];

    // ---- x1 + sg (16-deep load batch) ----
    const float4* xr4 = (const float4*)(xg + (size_t)t * Dn);
    const float4* er4 = (const float4*)(emb + (size_t)it * Dn);
    float4 x1[8];
    float sp = 0.f;
    {
        float4 xv[8], ev[8];
        #pragma unroll
        for (int k = 0; k < 8; k++) xv[k] = xr4[lane + 32 * k];
        #pragma unroll
        for (int k = 0; k < 8; k++) ev[k] = __ldg(er4 + lane + 32 * k);
        #pragma unroll
        for (int k = 0; k < 8; k++) {
            x1[k] = blend4(xv[k], ev[k], g);
            sp += sig4(x1[k], sg4s[lane + 32 * k]);
        }
    }
    #pragma unroll
    for (int o = 16; o; o >>= 1) sp += __shfl_xor_sync(0xffffffffu, sp, o);
    const float sg = sp * (1.0f / 1024.0f);

    // ---- logits = Y + g(E - Y); argmax (exact repair) + softmax ----
    float2 Y  = *(const float2*)(gY + (size_t)t * Vn + 2 * lane);
    float2 Ev = __ldg((const float2*)(gE + it * Vn) + lane);
    float l0 = fmaf(g, Ev.x - Y.x, Y.x);
    float l1 = fmaf(g, Ev.y - Y.y, Y.y);
    float m = l0; int mi = 2 * lane;
    if (l1 > m) { m = l1; mi = 2 * lane + 1; }
    #pragma unroll
    for (int o = 16; o; o >>= 1) {
        float om = __shfl_xor_sync(0xffffffffu, m, o);
        int  omi = __shfl_xor_sync(0xffffffffu, mi, o);
        if (om > m || (om == m && omi < mi)) { m = om; mi = omi; }
    }
    float thr = m - RGAP;
    unsigned cm0 = __ballot_sync(0xffffffffu, l0 > thr);
    unsigned cm1 = __ballot_sync(0xffffffffu, l1 > thr);
    if (__popc(cm0) + __popc(cm1) > 1) {          // rare exact fp32 repair via x1 regs
        float best = -1e30f; int bi = Vn;
        #pragma unroll
        for (int half = 0; half < 2; half++) {
            unsigned mm = half ? cm1 : cm0;
            while (mm) {
                int v = 2 * (__ffs(mm) - 1) + half; mm &= mm - 1;
                const float4* wr = (const float4*)(hwp + (size_t)v * Dn);
                float s = 0.f;
                #pragma unroll
                for (int k = 0; k < 8; k++) {
                    float4 wv = __ldg(wr + lane + 32 * k);
                    s = fmaf(x1[k].x, wv.x, fmaf(x1[k].y, wv.y,
                        fmaf(x1[k].z, wv.z, fmaf(x1[k].w, wv.w, s))));
                }
                #pragma unroll
                for (int o = 16; o; o >>= 1) s += __shfl_xor_sync(0xffffffffu, s, o);
                if (s > best || (s == best && v < bi)) { best = s; bi = v; }
            }
        }
        mi = bi;
    }
    float e0 = __expf(l0 - m), e1 = __expf(l1 - m);
    float den = e0 + e1;
    #pragma unroll
    for (int o = 16; o; o >>= 1) den += __shfl_xor_sync(0xffffffffu, den, o);
    float rd = 1.0f / den;
    float p0 = e0 * rd, p1 = e1 * rd;
    if (has_idx && lane == 0) out[(size_t)idx_off + t] = (float)mi;

    // ---- sparse gather + blend + store ----
    unsigned m0 = __ballot_sync(0xffffffffu, p0 > PTHRESH);
    unsigned m1 = __ballot_sync(0xffffffffu, p1 > PTHRESH);
    float4 av[8];
    #pragma unroll
    for (int k = 0; k < 8; k++) av[k] = make_float4(0.f, 0.f, 0.f, 0.f);
    unsigned mm = m0;
    while (mm) {                                   // uniform trips (ballot)
        int bb = __ffs(mm) - 1; mm &= mm - 1;
        float p = __shfl_sync(0xffffffffu, p0, bb);
        const float4* er = (const float4*)(emb + (size_t)(2 * bb) * Dn);
        #pragma unroll
        for (int k = 0; k < 8; k++) {
            float4 e = __ldg(er + lane + 32 * k);
            av[k].x = fmaf(p, e.x, av[k].x); av[k].y = fmaf(p, e.y, av[k].y);
            av[k].z = fmaf(p, e.z, av[k].z); av[k].w = fmaf(p, e.w, av[k].w);
        }
    }
    mm = m1;
    while (mm) {
        int bb = __ffs(mm) - 1; mm &= mm - 1;
        float p = __shfl_sync(0xffffffffu, p1, bb);
        const float4* er = (const float4*)(emb + (size_t)(2 * bb + 1) * Dn);
        #pragma unroll
        for (int k = 0; k < 8; k++) {
            float4 e = __ldg(er + lane + 32 * k);
            av[k].x = fmaf(p, e.x, av[k].x); av[k].y = fmaf(p, e.y, av[k].y);
            av[k].z = fmaf(p, e.z, av[k].z); av[k].w = fmaf(p, e.w, av[k].w);
        }
    }
    float4* orow = (float4*)(out + (size_t)t * Dn);
    #pragma unroll
    for (int k = 0; k < 8; k++) {
        float4 rr;
        rr.x = fmaf(sg, av[k].x - x1[k].x, x1[k].x);
        rr.y = fmaf(sg, av[k].y - x1[k].y, x1[k].y);
        rr.z = fmaf(sg, av[k].z - x1[k].z, x1[k].z);
        rr.w = fmaf(sg, av[k].w - x1[k].w, x1[k].w);
        orow[lane + 32 * k] = rr;
    }
}

extern "C" void kernel_launch(void* const* d_in, const int* in_sizes, int n_in,
                              void* d_out, int out_size) {
    (void)n_in;
    const float* x     = (const float*)d_in[0];
    const int*   idx   = (const int*)d_in[1];
    const float* emb   = (const float*)d_in[2];
    const float* hwp   = (const float*)d_in[3];
    const float* gate  = (const float*)d_in[4];
    const float* sgate = (const float*)d_in[5];
    float* out = (float*)d_out;

    const int n_tok   = in_sizes[0] / Dn;
    const int idx_off = in_sizes[0];
    const int has_idx = (out_size >= idx_off + n_tok) ? 1 : 0;

    cudaFuncSetAttribute(k_gemm, cudaFuncAttributeMaxDynamicSharedMemorySize, S_TOT);
    k_prepw<<<(Vn * Dn) / 256, 256>>>(hwp);
    k_prepe<<<Vn, 256>>>(emb, hwp);
    k_gemm<<<n_tok / TM, NT, S_TOT>>>(x, gate);
    k_post<<<n_tok / 8, 256>>>(x, idx, emb, hwp, sgate, out, idx_off, has_idx);
}